// round 7
// baseline (speedup 1.0000x reference)
#include <cuda_runtime.h>
#include <math.h>

// BarycentricCoordinates: V=6000 x (R*A)=40 items, N=16 projections each.
// One thread per item.
//
// Bit-exactness model (validated R4-R6, rel_err == 0.0):
//  - einsum dot products (K=2): dot = __fmaf_rn(y,y', __fmul_rn(x,x'))
//  - all other elementwise ops: strict IEEE mul/sub/div/sqrt, no contraction.
//
// R7: hot 120-pair loop runs two pairs per step with packed f32x2 ops (FFMA2:
// 2 IEEE-identical lane results per fma-pipe slot). Self-pair boundary lanes
// have exactly-zero numerators -> auto-rejected by the sign gate. Scalar tail
// (gates, rcp.approx score, top-2) reads packed halves for free. Exact top-2
// epilogue unchanged; cold exact-scalar path covers the no-candidate case.

#define MULF(a,b)   __fmul_rn((a),(b))
#define ADDF(a,b)   __fadd_rn((a),(b))
#define SUBF(a,b)   __fsub_rn((a),(b))
#define DIVF(a,b)   __fdiv_rn((a),(b))
#define DOT2(ax,ay,bx,by) __fmaf_rn((ay),(by), __fmul_rn((ax),(bx)))

typedef unsigned long long u64;
#define PACK2(d, lo, hi)   asm("mov.b64 %0, {%1,%2};" : "=l"(d) : "f"(lo), "f"(hi))
#define UNPK2(lo, hi, s)   asm("mov.b64 {%0,%1}, %2;" : "=f"(lo), "=f"(hi) : "l"(s))
#define MUL2(d,a,b)        asm("mul.rn.f32x2 %0, %1, %2;" : "=l"(d) : "l"(a), "l"(b))
#define FMA2(d,a,b,c)      asm("fma.rn.f32x2 %0, %1, %2, %3;" : "=l"(d) : "l"(a), "l"(b), "l"(c))
// a - b == fma(b, -1, a): single rounding, bit-identical to IEEE subtraction
#define SUB2(d,a,b)        FMA2(d, b, NEG1, a)

__global__ __launch_bounds__(128, 4)
void bc_kernel(const float* __restrict__ tmpl,
               const float* __restrict__ proj,
               float* __restrict__ out, int V)
{
    __shared__ float2 s_e[16][128];   // (ex, ey)
    __shared__ float2 s_d[16][128];   // (d00, d02)
    __shared__ float  s_dist[16][128];

    const int RA = 40;
    int tid = threadIdx.x;
    int gid = blockIdx.x * blockDim.x + tid;
    if (gid >= V * RA) return;        // exact grid: never diverges
    int v  = gid / RA;
    int ra = gid - v * RA;

    float tx = __ldg(tmpl + 2 * ra);
    float ty = __ldg(tmpl + 2 * ra + 1);

    float px[16], py[16];
    const float4* pp = (const float4*)(proj + (size_t)v * 32);
    #pragma unroll
    for (int k = 0; k < 8; k++) {
        float4 q = __ldg(pp + k);
        px[2*k]   = q.x; py[2*k]   = q.y;
        px[2*k+1] = q.z; py[2*k+1] = q.w;
    }

    // dist: strict IEEE; stash in smem for epilogue, regs die after the scan.
    float dist[16];
    #pragma unroll
    for (int i = 0; i < 16; i++) {
        float dx = SUBF(tx, px[i]), dy = SUBF(ty, py[i]);
        dist[i] = __fsqrt_rn(ADDF(MULF(dx,dx), MULF(dy,dy)));
        s_dist[i][tid] = dist[i];
    }

    // Stable two-min scan (branchless): closest (bi,bx,by) and 2nd (si)
    float bd = dist[0], bx = px[0], by = py[0], sd = INFINITY;
    int bi = 0, si = 0;
    #pragma unroll
    for (int i = 1; i < 16; i++) {
        bool lb = dist[i] < bd;
        bool ls = dist[i] < sd;
        sd = lb ? bd : (ls ? dist[i] : sd);
        si = lb ? bi : (ls ? i       : si);
        bd = lb ? dist[i] : bd;
        bx = lb ? px[i]   : bx;
        by = lb ? py[i]   : by;
        bi = lb ? i       : bi;
    }

    float v2x = SUBF(tx, bx), v2y = SUBF(ty, by);

    // Compute e/d, store smem, and pack pairwise (scalars die immediately).
    u64 EXJ[8], EYJ[8], D00J[8], D02J[8];
    #pragma unroll
    for (int k = 0; k < 8; k++) {
        int a = 2*k, b = 2*k+1;
        float exa = SUBF(px[a], bx), eya = SUBF(py[a], by);
        float exb = SUBF(px[b], bx), eyb = SUBF(py[b], by);
        float d00a = DOT2(exa, eya, exa, eya);
        float d02a = DOT2(exa, eya, v2x, v2y);
        float d00b = DOT2(exb, eyb, exb, eyb);
        float d02b = DOT2(exb, eyb, v2x, v2y);
        s_e[a][tid] = make_float2(exa, eya);
        s_e[b][tid] = make_float2(exb, eyb);
        s_d[a][tid] = make_float2(d00a, d02a);
        s_d[b][tid] = make_float2(d00b, d02b);
        PACK2(EXJ[k],  exa,  exb);
        PACK2(EYJ[k],  eya,  eyb);
        PACK2(D00J[k], d00a, d00b);
        PACK2(D02J[k], d02a, d02b);
    }

    u64 NEG1, C1E5;
    PACK2(NEG1, -1.0f, -1.0f);
    PACK2(C1E5, 1e-5f, 1e-5f);

    // ---- approximate top-2 pair search: packed f32x2, 2 pairs/step ----
    float s1 = INFINITY, s2 = INFINITY;
    int   id1 = -1,      id2 = -1;

    #pragma unroll
    for (int i = 0; i < 15; i++) {
        const int k0 = (i + 1) >> 1;   // even i: lane (i,i) self-invalidates
        // broadcast packs from packed halves (half reads are free in SASS)
        float xi, yi, ai, ci, t_lo, t_hi;
        UNPK2(t_lo, t_hi, EXJ[i >> 1]);  xi = (i & 1) ? t_hi : t_lo;
        UNPK2(t_lo, t_hi, EYJ[i >> 1]);  yi = (i & 1) ? t_hi : t_lo;
        UNPK2(t_lo, t_hi, D00J[i >> 1]); ai = (i & 1) ? t_hi : t_lo;
        UNPK2(t_lo, t_hi, D02J[i >> 1]); ci = (i & 1) ? t_hi : t_lo;
        u64 EXI, EYI, D00I, D02I;
        PACK2(EXI, xi, xi);
        PACK2(EYI, yi, yi);
        PACK2(D00I, ai, ai);
        PACK2(D02I, ci, ci);

        #pragma unroll
        for (int k = k0; k < 8; k++) {
            u64 t0, t1, d01P, denP, nAP, nBP, p0nP, den2P, gAP, gBP, gPP, qAP, qBP, qPP;
            MUL2(t0, EXI, EXJ[k]);
            FMA2(d01P, EYI, EYJ[k], t0);                 // exact einsum bits
            MUL2(t0, D00I, D00J[k]);
            MUL2(t1, d01P, d01P);
            SUB2(denP, t0, t1);                          // exact bits
            MUL2(t0, D02I, D00J[k]);
            MUL2(t1, d01P, D02J[k]);
            SUB2(nAP, t0, t1);                           // exact bits
            MUL2(t0, D00I, D02J[k]);
            MUL2(t1, d01P, D02I);
            SUB2(nBP, t0, t1);                           // exact bits
            SUB2(p0nP, denP, nAP);
            SUB2(p0nP, p0nP, nBP);                       // ~ p0*den (approx ok)
            MUL2(den2P, denP, denP);
            MUL2(gAP, nAP, denP);                        // sign gates
            MUL2(gBP, nBP, denP);
            MUL2(t0, den2P, C1E5);
            FMA2(gPP, p0nP, denP, t0);                   // conservative p0 gate
            MUL2(qAP, nAP, nAP);
            MUL2(qBP, nBP, nBP);
            MUL2(qPP, p0nP, p0nP);

            float gA0,gA1,gB0,gB1,gP0,gP1,qA0,qA1,qB0,qB1,qP0,qP1,dn0,dn1;
            UNPK2(gA0,gA1,gAP); UNPK2(gB0,gB1,gBP); UNPK2(gP0,gP1,gPP);
            UNPK2(qA0,qA1,qAP); UNPK2(qB0,qB1,qBP); UNPK2(qP0,qP1,qPP);
            UNPK2(dn0,dn1,den2P);
            {
                float m  = fminf(fminf(gA0, gB0), gP0);
                float sN = fmaxf(fmaxf(qA0, qB0), qP0);
                float r; asm("rcp.approx.f32 %0, %1;" : "=f"(r) : "f"(dn0));
                float s = sN * r;
                s = (m > 0.0f) ? s : INFINITY;
                int code = i * 16 + 2 * k;
                bool b1 = s < s1, b2 = s < s2;
                s2  = b1 ? s1  : (b2 ? s    : s2);
                id2 = b1 ? id1 : (b2 ? code : id2);
                s1  = b1 ? s   : s1;
                id1 = b1 ? code : id1;
            }
            {
                float m  = fminf(fminf(gA1, gB1), gP1);
                float sN = fmaxf(fmaxf(qA1, qB1), qP1);
                float r; asm("rcp.approx.f32 %0, %1;" : "=f"(r) : "f"(dn1));
                float s = sN * r;
                s = (m > 0.0f) ? s : INFINITY;
                int code = i * 16 + 2 * k + 1;
                bool b1 = s < s1, b2 = s < s2;
                s2  = b1 ? s1  : (b2 ? s    : s2);
                id2 = b1 ? id1 : (b2 ? code : id2);
                s1  = b1 ? s   : s1;
                id1 = b1 ? code : id1;
            }
        }
    }

    // ---- exact resolution ----
    float w0 = 0.f, w1 = 0.f, w2 = 0.f;
    int   o1 = si, o2 = si;
    float bestS = INFINITY;

    if (id1 >= 0) {
        // hot: re-evaluate top-2 candidates bit-exactly (smem gather)
        #pragma unroll
        for (int c = 0; c < 2; c++) {
            int code = (c == 0) ? id1 : id2;
            if (code >= 0) {
                int ip = code >> 4, jp = code & 15;
                float2 eiv = s_e[ip][tid], ejv = s_e[jp][tid];
                float2 div = s_d[ip][tid], djv = s_d[jp][tid];
                float  di  = s_dist[ip][tid], dj = s_dist[jp][tid];
                float d01 = DOT2(eiv.x, eiv.y, ejv.x, ejv.y);
                float den = SUBF(MULF(div.x,djv.x), MULF(d01,d01));
                if (den == 0.0f) den = 1e-10f;
                float nA = SUBF(MULF(div.y,djv.x), MULF(d01,djv.y));
                float nB = SUBF(MULF(div.x,djv.y), MULF(d01,div.y));
                bool candx = (den > 0.0f) ? (nA > 0.0f && nB > 0.0f)
                                          : (nA < 0.0f && nB < 0.0f);
                if (candx) {
                    float pA = DIVF(nA, den);            // exact IEEE divide
                    float pB = DIVF(nB, den);
                    float m2  = fmaxf(MULF(pA,pA), MULF(pB,pB));
                    float p0i = SUBF(SUBF(1.0f, pA), pB);
                    float p0j = SUBF(SUBF(1.0f, pB), pA);
                    float siS = (p0i > 0.f) ? fmaxf(MULF(p0i,p0i), m2) : INFINITY;
                    float sjS = (p0j > 0.f) ? fmaxf(MULF(p0j,p0j), m2) : INFINITY;
                    bool iFirst = (di <= dj);
                    float sLow  = iFirst ? siS : sjS;
                    float sHigh = iFirst ? sjS : siS;
                    bool pickLow = (sLow <= sHigh);
                    float s = pickLow ? sLow : sHigh;
                    if (s < bestS) {
                        bestS = s;
                        bool icell = pickLow ? iFirst : !iFirst;
                        if (icell) { w0 = p0i; w1 = pA; w2 = pB; o1 = ip; o2 = jp; }
                        else       { w0 = p0j; w1 = pB; w2 = pA; o1 = jp; o2 = ip; }
                    }
                }
            }
        }
    } else {
        // cold: no approx candidate (covers legit den==0-only items too):
        // exact full scalar pass over all pairs from smem.
        #pragma unroll 1
        for (int ip = 0; ip < 15; ip++) {
            float2 eiv = s_e[ip][tid];
            float2 div = s_d[ip][tid];
            float  di  = s_dist[ip][tid];
            #pragma unroll 1
            for (int jp = ip + 1; jp < 16; jp++) {
                float2 ejv = s_e[jp][tid];
                float2 djv = s_d[jp][tid];
                float  dj  = s_dist[jp][tid];
                float d01 = DOT2(eiv.x, eiv.y, ejv.x, ejv.y);
                float den = SUBF(MULF(div.x,djv.x), MULF(d01,d01));
                if (den == 0.0f) den = 1e-10f;
                float nA = SUBF(MULF(div.y,djv.x), MULF(d01,djv.y));
                float nB = SUBF(MULF(div.x,djv.y), MULF(d01,div.y));
                bool candx = (den > 0.0f) ? (nA > 0.0f && nB > 0.0f)
                                          : (nA < 0.0f && nB < 0.0f);
                if (candx) {
                    float pA = DIVF(nA, den);
                    float pB = DIVF(nB, den);
                    float m2  = fmaxf(MULF(pA,pA), MULF(pB,pB));
                    float p0i = SUBF(SUBF(1.0f, pA), pB);
                    float p0j = SUBF(SUBF(1.0f, pB), pA);
                    float siS = (p0i > 0.f) ? fmaxf(MULF(p0i,p0i), m2) : INFINITY;
                    float sjS = (p0j > 0.f) ? fmaxf(MULF(p0j,p0j), m2) : INFINITY;
                    bool iFirst = (di <= dj);
                    float sLow  = iFirst ? siS : sjS;
                    float sHigh = iFirst ? sjS : siS;
                    bool pickLow = (sLow <= sHigh);
                    float s = pickLow ? sLow : sHigh;
                    if (s < bestS) {
                        bestS = s;
                        bool icell = pickLow ? iFirst : !iFirst;
                        if (icell) { w0 = p0i; w1 = pA; w2 = pB; o1 = ip; o2 = jp; }
                        else       { w0 = p0j; w1 = pB; w2 = pA; o1 = jp; o2 = ip; }
                    }
                }
            }
        }
    }

    if (!(bestS < INFINITY)) {   // no valid pair: reference fallback
        w0 = 0.f; w1 = 0.f; w2 = 0.f; o1 = si; o2 = si;
    }

    float* ow = out + (size_t)gid * 3;
    ow[0] = w0; ow[1] = w1; ow[2] = w2;
    float* oi = out + (size_t)V * RA * 3 + (size_t)gid * 3;
    oi[0] = (float)bi; oi[1] = (float)o1; oi[2] = (float)o2;
}

extern "C" void kernel_launch(void* const* d_in, const int* in_sizes, int n_in,
                              void* d_out, int out_size)
{
    const float* tmpl = (const float*)d_in[0];   // (5,8,2) = 80 floats
    const float* proj = (const float*)d_in[1];   // (V,16,2)
    int V = in_sizes[1] / 32;
    int total = V * 40;
    int threads = 128;
    int blocks = (total + threads - 1) / threads;
    bc_kernel<<<blocks, threads>>>(tmpl, proj, (float*)d_out, V);
}

// round 8
// speedup vs baseline: 1.0003x; 1.0003x over previous
#include <cuda_runtime.h>
#include <math.h>

// BarycentricCoordinates: V=6000 x (R*A)=40 items, N=16 projections each.
// One thread per item.
//
// Bit-exactness model (validated R4-R6, rel_err == 0.0):
//  - einsum dot products (K=2): dot = __fmaf_rn(y,y', __fmul_rn(x,x'))
//  - all other elementwise ops: strict IEEE mul/sub/div/sqrt, no contraction.
//
// R8: occupancy-first rebuild of the R6 scalar kernel.
//  - all per-point operands (ex,ey,d00,d02) live ONLY in smem (float4, const
//    offsets, conflict-free); dist[] eliminated (streaming two-min; epilogue
//    recomputes the 2 needed dists from L1-hot global).
//  - hot loop tracks top-2 via sortable int keys (pair code embedded in low 8
//    mantissa bits) with 3 IMNMX/pair instead of 8 FSETP/SEL.
//  - exact top-2 epilogue (IEEE divides, two-cell argmin) unchanged; cold
//    exact full scan (with the den==0 -> 1e-10 patch) covers no-candidate items.

#define MULF(a,b)   __fmul_rn((a),(b))
#define ADDF(a,b)   __fadd_rn((a),(b))
#define SUBF(a,b)   __fsub_rn((a),(b))
#define DIVF(a,b)   __fdiv_rn((a),(b))
#define DOT2(ax,ay,bx,by) __fmaf_rn((ay),(by), __fmul_rn((ax),(bx)))

#define KEY_SENTINEL 0x7FFFFFFFu

__global__ __launch_bounds__(128, 6)
void bc_kernel(const float* __restrict__ tmpl,
               const float* __restrict__ proj,
               float* __restrict__ out, int V)
{
    __shared__ float4 s_ed[16][128];   // (ex, ey, d00, d02) per point per thread

    const int RA = 40;
    int tid = threadIdx.x;
    int gid = blockIdx.x * blockDim.x + tid;
    if (gid >= V * RA) return;        // exact grid: never diverges
    int v  = gid / RA;
    int ra = gid - v * RA;

    float tx = __ldg(tmpl + 2 * ra);
    float ty = __ldg(tmpl + 2 * ra + 1);
    const float4* pp = (const float4*)(proj + (size_t)v * 32);

    // ---- pass 1: streaming stable two-min over dist (strict IEEE bits) ----
    float bd = INFINITY, sd = INFINITY, bx = 0.f, by = 0.f;
    int bi = 0, si = 0;
    #pragma unroll
    for (int k = 0; k < 8; k++) {
        float4 q = __ldg(pp + k);
        {
            float dx = SUBF(tx, q.x), dy = SUBF(ty, q.y);
            float d = __fsqrt_rn(ADDF(MULF(dx,dx), MULF(dy,dy)));
            bool lb = d < bd, ls = d < sd;
            sd = lb ? bd : (ls ? d : sd);
            si = lb ? bi : (ls ? 2*k : si);
            bd = lb ? d : bd;  bx = lb ? q.x : bx;  by = lb ? q.y : by;
            bi = lb ? 2*k : bi;
        }
        {
            float dx = SUBF(tx, q.z), dy = SUBF(ty, q.w);
            float d = __fsqrt_rn(ADDF(MULF(dx,dx), MULF(dy,dy)));
            bool lb = d < bd, ls = d < sd;
            sd = lb ? bd : (ls ? d : sd);
            si = lb ? bi : (ls ? 2*k+1 : si);
            bd = lb ? d : bd;  bx = lb ? q.z : bx;  by = lb ? q.w : by;
            bi = lb ? 2*k+1 : bi;
        }
    }

    // ---- pass 2: ex/ey/d00/d02 -> smem only (exact bits) ----
    float v2x = SUBF(tx, bx), v2y = SUBF(ty, by);
    #pragma unroll
    for (int k = 0; k < 8; k++) {
        float4 q = __ldg(pp + k);
        {
            float ex = SUBF(q.x, bx), ey = SUBF(q.y, by);
            float d00 = DOT2(ex, ey, ex, ey);
            float d02 = DOT2(ex, ey, v2x, v2y);
            s_ed[2*k][tid] = make_float4(ex, ey, d00, d02);
        }
        {
            float ex = SUBF(q.z, bx), ey = SUBF(q.w, by);
            float d00 = DOT2(ex, ey, ex, ey);
            float d02 = DOT2(ex, ey, v2x, v2y);
            s_ed[2*k+1][tid] = make_float4(ex, ey, d00, d02);
        }
    }

    // ---- hot loop: approximate scoring, top-2 via int keys ----
    unsigned k1 = KEY_SENTINEL, k2 = KEY_SENTINEL;

    #pragma unroll
    for (int i = 0; i < 15; i++) {
        float4 fi = s_ed[i][tid];
        #pragma unroll
        for (int j = i + 1; j < 16; j++) {
            float4 fj = s_ed[j][tid];
            float d01 = DOT2(fi.x, fi.y, fj.x, fj.y);            // exact bits
            float den = SUBF(MULF(fi.z,fj.z), MULF(d01,d01));    // exact bits
            float nA  = SUBF(MULF(fi.w,fj.z), MULF(d01,fj.w));   // exact bits
            float nB  = SUBF(MULF(fi.z,fj.w), MULF(d01,fi.w));   // exact bits
            float p0n  = SUBF(SUBF(den, nA), nB);   // ~ p0*den (approx ok)
            float den2 = den * den;
            float gA = nA * den;                    // sign-exact gates
            float gB = nB * den;
            float gP = __fmaf_rn(p0n, den, 1e-5f * den2);  // conservative p0
            float m  = fminf(fminf(gA, gB), gP);
            float amax = fmaxf(fabsf(nA), fmaxf(fabsf(nB), fabsf(p0n)));
            float sNum = amax * amax;
            float r; asm("rcp.approx.f32 %0, %1;" : "=f"(r) : "f"(den2));
            float s = sNum * r;                     // >= 0
            unsigned key = (m > 0.0f)
                ? ((__float_as_uint(s) & 0xFFFFFF00u) | (unsigned)(i * 16 + j))
                : KEY_SENTINEL;
            unsigned mx = umax(k1, key);
            k1 = umin(k1, key);
            k2 = umin(k2, mx);
        }
    }

    // ---- exact resolution ----
    float w0 = 0.f, w1 = 0.f, w2 = 0.f;
    int   o1 = si, o2 = si;
    float bestS = INFINITY;

    if (k1 != KEY_SENTINEL) {
        #pragma unroll
        for (int c = 0; c < 2; c++) {
            unsigned key = (c == 0) ? k1 : k2;
            if (key != KEY_SENTINEL) {
                int code = (int)(key & 255u);
                int ip = code >> 4, jp = code & 15;
                float4 fi = s_ed[ip][tid];
                float4 fj = s_ed[jp][tid];
                // recompute the two dists (exact bits) from L1-hot global
                float4 qi = __ldg(pp + (ip >> 1));
                float pxi = (ip & 1) ? qi.z : qi.x;
                float pyi = (ip & 1) ? qi.w : qi.y;
                float4 qj = __ldg(pp + (jp >> 1));
                float pxj = (jp & 1) ? qj.z : qj.x;
                float pyj = (jp & 1) ? qj.w : qj.y;
                float dxi = SUBF(tx,pxi), dyi = SUBF(ty,pyi);
                float di  = __fsqrt_rn(ADDF(MULF(dxi,dxi), MULF(dyi,dyi)));
                float dxj = SUBF(tx,pxj), dyj = SUBF(ty,pyj);
                float dj  = __fsqrt_rn(ADDF(MULF(dxj,dxj), MULF(dyj,dyj)));

                float d01 = DOT2(fi.x, fi.y, fj.x, fj.y);
                float den = SUBF(MULF(fi.z,fj.z), MULF(d01,d01));
                if (den == 0.0f) den = 1e-10f;
                float nA = SUBF(MULF(fi.w,fj.z), MULF(d01,fj.w));
                float nB = SUBF(MULF(fi.z,fj.w), MULF(d01,fi.w));
                bool candx = (den > 0.0f) ? (nA > 0.0f && nB > 0.0f)
                                          : (nA < 0.0f && nB < 0.0f);
                if (candx) {
                    float pA = DIVF(nA, den);            // exact IEEE divide
                    float pB = DIVF(nB, den);
                    float m2  = fmaxf(MULF(pA,pA), MULF(pB,pB));
                    float p0i = SUBF(SUBF(1.0f, pA), pB);
                    float p0j = SUBF(SUBF(1.0f, pB), pA);
                    float siS = (p0i > 0.f) ? fmaxf(MULF(p0i,p0i), m2) : INFINITY;
                    float sjS = (p0j > 0.f) ? fmaxf(MULF(p0j,p0j), m2) : INFINITY;
                    bool iFirst = (di <= dj);
                    float sLow  = iFirst ? siS : sjS;
                    float sHigh = iFirst ? sjS : siS;
                    bool pickLow = (sLow <= sHigh);
                    float s = pickLow ? sLow : sHigh;
                    if (s < bestS) {
                        bestS = s;
                        bool icell = pickLow ? iFirst : !iFirst;
                        if (icell) { w0 = p0i; w1 = pA; w2 = pB; o1 = ip; o2 = jp; }
                        else       { w0 = p0j; w1 = pB; w2 = pA; o1 = jp; o2 = ip; }
                    }
                }
            }
        }
    } else {
        // cold: no approx candidate. Exact full scan incl. den==0 patch.
        float dist[16];
        #pragma unroll 1
        for (int k = 0; k < 8; k++) {
            float4 q = __ldg(pp + k);
            float dx0 = SUBF(tx,q.x), dy0 = SUBF(ty,q.y);
            dist[2*k]   = __fsqrt_rn(ADDF(MULF(dx0,dx0), MULF(dy0,dy0)));
            float dx1 = SUBF(tx,q.z), dy1 = SUBF(ty,q.w);
            dist[2*k+1] = __fsqrt_rn(ADDF(MULF(dx1,dx1), MULF(dy1,dy1)));
        }
        #pragma unroll 1
        for (int ip = 0; ip < 15; ip++) {
            float4 fi = s_ed[ip][tid];
            float  di = dist[ip];
            #pragma unroll 1
            for (int jp = ip + 1; jp < 16; jp++) {
                float4 fj = s_ed[jp][tid];
                float  dj = dist[jp];
                float d01 = DOT2(fi.x, fi.y, fj.x, fj.y);
                float den = SUBF(MULF(fi.z,fj.z), MULF(d01,d01));
                if (den == 0.0f) den = 1e-10f;
                float nA = SUBF(MULF(fi.w,fj.z), MULF(d01,fj.w));
                float nB = SUBF(MULF(fi.z,fj.w), MULF(d01,fi.w));
                bool candx = (den > 0.0f) ? (nA > 0.0f && nB > 0.0f)
                                          : (nA < 0.0f && nB < 0.0f);
                if (candx) {
                    float pA = DIVF(nA, den);
                    float pB = DIVF(nB, den);
                    float m2  = fmaxf(MULF(pA,pA), MULF(pB,pB));
                    float p0i = SUBF(SUBF(1.0f, pA), pB);
                    float p0j = SUBF(SUBF(1.0f, pB), pA);
                    float siS = (p0i > 0.f) ? fmaxf(MULF(p0i,p0i), m2) : INFINITY;
                    float sjS = (p0j > 0.f) ? fmaxf(MULF(p0j,p0j), m2) : INFINITY;
                    bool iFirst = (di <= dj);
                    float sLow  = iFirst ? siS : sjS;
                    float sHigh = iFirst ? sjS : siS;
                    bool pickLow = (sLow <= sHigh);
                    float s = pickLow ? sLow : sHigh;
                    if (s < bestS) {
                        bestS = s;
                        bool icell = pickLow ? iFirst : !iFirst;
                        if (icell) { w0 = p0i; w1 = pA; w2 = pB; o1 = ip; o2 = jp; }
                        else       { w0 = p0j; w1 = pB; w2 = pA; o1 = jp; o2 = ip; }
                    }
                }
            }
        }
    }

    if (!(bestS < INFINITY)) {   // no valid pair: reference fallback
        w0 = 0.f; w1 = 0.f; w2 = 0.f; o1 = si; o2 = si;
    }

    float* ow = out + (size_t)gid * 3;
    ow[0] = w0; ow[1] = w1; ow[2] = w2;
    float* oi = out + (size_t)V * RA * 3 + (size_t)gid * 3;
    oi[0] = (float)bi; oi[1] = (float)o1; oi[2] = (float)o2;
}

extern "C" void kernel_launch(void* const* d_in, const int* in_sizes, int n_in,
                              void* d_out, int out_size)
{
    const float* tmpl = (const float*)d_in[0];   // (5,8,2) = 80 floats
    const float* proj = (const float*)d_in[1];   // (V,16,2)
    int V = in_sizes[1] / 32;
    int total = V * 40;
    int threads = 128;
    int blocks = (total + threads - 1) / threads;
    bc_kernel<<<blocks, threads>>>(tmpl, proj, (float*)d_out, V);
}

// round 9
// speedup vs baseline: 1.1957x; 1.1953x over previous
#include <cuda_runtime.h>
#include <math.h>

// BarycentricCoordinates: V=6000 x (R*A)=40 items, N=16 projections each.
// One thread per item.
//
// Bit-exactness model (validated R4-R6, rel_err == 0.0):
//  - einsum dot products (K=2): dot = __fmaf_rn(y,y', __fmul_rn(x,x'))
//  - all other elementwise ops: strict IEEE mul/sub/div/sqrt, no contraction.
//
// R9: 2-D cross-product hot loop, operands in REGISTERS (R8 lesson).
//   c = e_i x e_j, u_k = v2 x e_k (per-point!). Real arithmetic:
//   p2 = u_j/c, p1 = -u_i/c, p0 = (c - u_j + u_i)/c.
//   Approximate pass: conservative weight-space margin (1e-4) so borderline
//   pairs are ACCEPTED; score = max(|u_i|,|u_j|,|q|)^2 * rcp(c^2) (MUFU).
//   Full-float top-2 tracking (no key truncation). Exact epilogue re-evaluates
//   top-2 with the reference-bit formulas; if both fail, cold exact full scan.
//   d00/d02 (exact bits) parked in smem only for epilogue/cold use.

#define MULF(a,b)   __fmul_rn((a),(b))
#define ADDF(a,b)   __fadd_rn((a),(b))
#define SUBF(a,b)   __fsub_rn((a),(b))
#define DIVF(a,b)   __fdiv_rn((a),(b))
#define DOT2(ax,ay,bx,by) __fmaf_rn((ay),(by), __fmul_rn((ax),(bx)))

__global__ __launch_bounds__(128, 5)
void bc_kernel(const float* __restrict__ tmpl,
               const float* __restrict__ proj,
               float* __restrict__ out, int V)
{
    __shared__ float4 s_ed[16][128];   // (ex, ey, d00, d02) exact bits

    const int RA = 40;
    int tid = threadIdx.x;
    int gid = blockIdx.x * blockDim.x + tid;
    if (gid >= V * RA) return;        // exact grid: never diverges
    int v  = gid / RA;
    int ra = gid - v * RA;

    float tx = __ldg(tmpl + 2 * ra);
    float ty = __ldg(tmpl + 2 * ra + 1);
    const float4* pp = (const float4*)(proj + (size_t)v * 32);

    float4 Q[8];
    #pragma unroll
    for (int k = 0; k < 8; k++) Q[k] = __ldg(pp + k);

    // ---- streaming stable two-min over exact-bit dist ----
    float bd = INFINITY, sd = INFINITY, bx = 0.f, by = 0.f;
    int bi = 0, si = 0;
    #pragma unroll
    for (int k = 0; k < 8; k++) {
        {
            float dx = SUBF(tx, Q[k].x), dy = SUBF(ty, Q[k].y);
            float d = __fsqrt_rn(ADDF(MULF(dx,dx), MULF(dy,dy)));
            bool lb = d < bd, ls = d < sd;
            sd = lb ? bd : (ls ? d : sd);
            si = lb ? bi : (ls ? 2*k : si);
            bd = lb ? d : bd;  bx = lb ? Q[k].x : bx;  by = lb ? Q[k].y : by;
            bi = lb ? 2*k : bi;
        }
        {
            float dx = SUBF(tx, Q[k].z), dy = SUBF(ty, Q[k].w);
            float d = __fsqrt_rn(ADDF(MULF(dx,dx), MULF(dy,dy)));
            bool lb = d < bd, ls = d < sd;
            sd = lb ? bd : (ls ? d : sd);
            si = lb ? bi : (ls ? 2*k+1 : si);
            bd = lb ? d : bd;  bx = lb ? Q[k].z : bx;  by = lb ? Q[k].w : by;
            bi = lb ? 2*k+1 : bi;
        }
    }

    // ---- per-point: ex/ey/u in regs; exact d00/d02 -> smem for epilogue ----
    float v2x = SUBF(tx, bx), v2y = SUBF(ty, by);
    float ex[16], ey[16], u[16];
    #pragma unroll
    for (int k = 0; k < 8; k++) {
        {
            float e0 = SUBF(Q[k].x, bx), e1 = SUBF(Q[k].y, by);
            ex[2*k] = e0; ey[2*k] = e1;
            u[2*k]  = v2x * e1 - v2y * e0;            // approx path only
            float d00 = DOT2(e0, e1, e0, e1);         // exact bits
            float d02 = DOT2(e0, e1, v2x, v2y);       // exact bits
            s_ed[2*k][tid] = make_float4(e0, e1, d00, d02);
        }
        {
            float e0 = SUBF(Q[k].z, bx), e1 = SUBF(Q[k].w, by);
            ex[2*k+1] = e0; ey[2*k+1] = e1;
            u[2*k+1]  = v2x * e1 - v2y * e0;
            float d00 = DOT2(e0, e1, e0, e1);
            float d02 = DOT2(e0, e1, v2x, v2y);
            s_ed[2*k+1][tid] = make_float4(e0, e1, d00, d02);
        }
    }

    // ---- hot loop: cross-form approximate scoring, full-float top-2 ----
    float s1 = INFINITY, s2 = INFINITY;
    int   id1 = -1,      id2 = -1;

    #pragma unroll
    for (int i = 0; i < 15; i++) {
        float exi = ex[i], eyi = ey[i], ui = u[i];
        float aui = fabsf(ui);
        #pragma unroll
        for (int j = i + 1; j < 16; j++) {
            float c  = exi * ey[j] - eyi * ex[j];   // pairs w/ closest: c == 0
            float c2 = c * c;
            float e  = 1e-4f * c2;                  // weight-space margin
            float q  = c - u[j] + ui;               // ~ p0 * c
            float gU = u[j] * c + e;                // p2 > -1e-4
            float gV = e - ui * c;                  // p1 > -1e-4
            float gQ = q * c + e;                   // p0 > -1e-4
            float m  = fminf(fminf(gU, gV), gQ);
            float am = fmaxf(fmaxf(aui, fabsf(u[j])), fabsf(q));
            float r;  asm("rcp.approx.f32 %0, %1;" : "=f"(r) : "f"(c2));
            float s  = (am * am) * r;
            bool valid = m > 0.0f;
            bool b1 = valid && (s < s1);
            bool b2 = valid && (s < s2);
            int code = i * 16 + j;
            s2  = b1 ? s1  : (b2 ? s    : s2);
            id2 = b1 ? id1 : (b2 ? code : id2);
            s1  = b1 ? s    : s1;
            id1 = b1 ? code : id1;
        }
    }

    // ---- exact resolution of top-2 candidates ----
    float w0 = 0.f, w1 = 0.f, w2 = 0.f;
    int   o1 = si, o2 = si;
    float bestS = INFINITY;

    #pragma unroll
    for (int c = 0; c < 2; c++) {
        int code = (c == 0) ? id1 : id2;
        if (code >= 0) {
            int ip = code >> 4, jp = code & 15;
            float4 fi = s_ed[ip][tid];
            float4 fj = s_ed[jp][tid];
            // exact dists for rank ordering (L1-hot reload)
            float4 qi = __ldg(pp + (ip >> 1));
            float pxi = (ip & 1) ? qi.z : qi.x, pyi = (ip & 1) ? qi.w : qi.y;
            float4 qj = __ldg(pp + (jp >> 1));
            float pxj = (jp & 1) ? qj.z : qj.x, pyj = (jp & 1) ? qj.w : qj.y;
            float dxi = SUBF(tx,pxi), dyi = SUBF(ty,pyi);
            float di  = __fsqrt_rn(ADDF(MULF(dxi,dxi), MULF(dyi,dyi)));
            float dxj = SUBF(tx,pxj), dyj = SUBF(ty,pyj);
            float dj  = __fsqrt_rn(ADDF(MULF(dxj,dxj), MULF(dyj,dyj)));

            float d01 = DOT2(fi.x, fi.y, fj.x, fj.y);           // exact bits
            float den = SUBF(MULF(fi.z,fj.z), MULF(d01,d01));
            if (den == 0.0f) den = 1e-10f;
            float nA = SUBF(MULF(fi.w,fj.z), MULF(d01,fj.w));
            float nB = SUBF(MULF(fi.z,fj.w), MULF(d01,fi.w));
            bool candx = (den > 0.0f) ? (nA > 0.0f && nB > 0.0f)
                                      : (nA < 0.0f && nB < 0.0f);
            if (candx) {
                float pA = DIVF(nA, den);                       // exact IEEE
                float pB = DIVF(nB, den);
                float m2  = fmaxf(MULF(pA,pA), MULF(pB,pB));
                float p0i = SUBF(SUBF(1.0f, pA), pB);
                float p0j = SUBF(SUBF(1.0f, pB), pA);
                float siS = (p0i > 0.f) ? fmaxf(MULF(p0i,p0i), m2) : INFINITY;
                float sjS = (p0j > 0.f) ? fmaxf(MULF(p0j,p0j), m2) : INFINITY;
                bool iFirst = (di <= dj);
                float sLow  = iFirst ? siS : sjS;
                float sHigh = iFirst ? sjS : siS;
                bool pickLow = (sLow <= sHigh);
                float s = pickLow ? sLow : sHigh;
                if (s < bestS) {
                    bestS = s;
                    bool icell = pickLow ? iFirst : !iFirst;
                    if (icell) { w0 = p0i; w1 = pA; w2 = pB; o1 = ip; o2 = jp; }
                    else       { w0 = p0j; w1 = pB; w2 = pA; o1 = jp; o2 = ip; }
                }
            }
        }
    }

    // ---- cold safety net: no candidate OR both exactly rejected ----
    if (!(bestS < INFINITY)) {
        float dist[16];
        #pragma unroll 1
        for (int k = 0; k < 8; k++) {
            float4 q = __ldg(pp + k);
            float dx0 = SUBF(tx,q.x), dy0 = SUBF(ty,q.y);
            dist[2*k]   = __fsqrt_rn(ADDF(MULF(dx0,dx0), MULF(dy0,dy0)));
            float dx1 = SUBF(tx,q.z), dy1 = SUBF(ty,q.w);
            dist[2*k+1] = __fsqrt_rn(ADDF(MULF(dx1,dx1), MULF(dy1,dy1)));
        }
        #pragma unroll 1
        for (int ip = 0; ip < 15; ip++) {
            float4 fi = s_ed[ip][tid];
            float  di = dist[ip];
            #pragma unroll 1
            for (int jp = ip + 1; jp < 16; jp++) {
                float4 fj = s_ed[jp][tid];
                float  dj = dist[jp];
                float d01 = DOT2(fi.x, fi.y, fj.x, fj.y);
                float den = SUBF(MULF(fi.z,fj.z), MULF(d01,d01));
                if (den == 0.0f) den = 1e-10f;
                float nA = SUBF(MULF(fi.w,fj.z), MULF(d01,fj.w));
                float nB = SUBF(MULF(fi.z,fj.w), MULF(d01,fi.w));
                bool candx = (den > 0.0f) ? (nA > 0.0f && nB > 0.0f)
                                          : (nA < 0.0f && nB < 0.0f);
                if (candx) {
                    float pA = DIVF(nA, den);
                    float pB = DIVF(nB, den);
                    float m2  = fmaxf(MULF(pA,pA), MULF(pB,pB));
                    float p0i = SUBF(SUBF(1.0f, pA), pB);
                    float p0j = SUBF(SUBF(1.0f, pB), pA);
                    float siS = (p0i > 0.f) ? fmaxf(MULF(p0i,p0i), m2) : INFINITY;
                    float sjS = (p0j > 0.f) ? fmaxf(MULF(p0j,p0j), m2) : INFINITY;
                    bool iFirst = (di <= dj);
                    float sLow  = iFirst ? siS : sjS;
                    float sHigh = iFirst ? sjS : siS;
                    bool pickLow = (sLow <= sHigh);
                    float s = pickLow ? sLow : sHigh;
                    if (s < bestS) {
                        bestS = s;
                        bool icell = pickLow ? iFirst : !iFirst;
                        if (icell) { w0 = p0i; w1 = pA; w2 = pB; o1 = ip; o2 = jp; }
                        else       { w0 = p0j; w1 = pB; w2 = pA; o1 = jp; o2 = ip; }
                    }
                }
            }
        }
        if (!(bestS < INFINITY)) {   // truly no valid pair: reference fallback
            w0 = 0.f; w1 = 0.f; w2 = 0.f; o1 = si; o2 = si;
        }
    }

    float* ow = out + (size_t)gid * 3;
    ow[0] = w0; ow[1] = w1; ow[2] = w2;
    float* oi = out + (size_t)V * RA * 3 + (size_t)gid * 3;
    oi[0] = (float)bi; oi[1] = (float)o1; oi[2] = (float)o2;
}

extern "C" void kernel_launch(void* const* d_in, const int* in_sizes, int n_in,
                              void* d_out, int out_size)
{
    const float* tmpl = (const float*)d_in[0];   // (5,8,2) = 80 floats
    const float* proj = (const float*)d_in[1];   // (V,16,2)
    int V = in_sizes[1] / 32;
    int total = V * 40;
    int threads = 128;
    int blocks = (total + threads - 1) / threads;
    bc_kernel<<<blocks, threads>>>(tmpl, proj, (float*)d_out, V);
}

// round 10
// speedup vs baseline: 1.2427x; 1.0394x over previous
#include <cuda_runtime.h>
#include <math.h>

// BarycentricCoordinates: V=6000 x (R*A)=40 items, N=16 projections each.
// One thread per item.
//
// Bit-exactness model (validated R4-R6/R9, rel_err == 0.0):
//  - einsum dot products (K=2): dot = __fmaf_rn(y,y', __fmul_rn(x,x'))
//  - all other elementwise ops: strict IEEE mul/sub/div/sqrt, no contraction.
//
// R10 = R6 skeleton (68.3us, no spills) + R9's cheaper cross-form hot loop:
//   c = e_i x e_j; u_k = v2 x e_k (per-point). Approx pass gates with a
//   conservative 1e-4 weight-space margin (borderline pairs ACCEPTED); score
//   = max(|u_i|,|u_j|,|q|)^2 * rcp(c^2) on the MUFU pipe. Full-float top-2.
//   Hot-loop operands ex/ey/u live in 48 REGISTERS (< R6's 64). Exact d00/d02
//   and dist live in smem for the exact top-2 epilogue / cold full scan.

#define MULF(a,b)   __fmul_rn((a),(b))
#define ADDF(a,b)   __fadd_rn((a),(b))
#define SUBF(a,b)   __fsub_rn((a),(b))
#define DIVF(a,b)   __fdiv_rn((a),(b))
#define DOT2(ax,ay,bx,by) __fmaf_rn((ay),(by), __fmul_rn((ax),(bx)))

__global__ __launch_bounds__(128, 4)
void bc_kernel(const float* __restrict__ tmpl,
               const float* __restrict__ proj,
               float* __restrict__ out, int V)
{
    __shared__ float2 s_d[16][128];   // (d00, d02) exact bits
    __shared__ float2 s_e[16][128];   // (ex, ey) exact bits
    __shared__ float  s_dist[16][128];

    const int RA = 40;
    int tid = threadIdx.x;
    int gid = blockIdx.x * blockDim.x + tid;
    if (gid >= V * RA) return;        // exact grid: never diverges
    int v  = gid / RA;
    int ra = gid - v * RA;

    float tx = __ldg(tmpl + 2 * ra);
    float ty = __ldg(tmpl + 2 * ra + 1);

    float px[16], py[16];
    const float4* pp = (const float4*)(proj + (size_t)v * 32);
    #pragma unroll
    for (int k = 0; k < 8; k++) {
        float4 q = __ldg(pp + k);
        px[2*k]   = q.x; py[2*k]   = q.y;
        px[2*k+1] = q.z; py[2*k+1] = q.w;
    }

    // dist: strict IEEE; smem for epilogue, regs die after the scan.
    float dist[16];
    #pragma unroll
    for (int i = 0; i < 16; i++) {
        float dx = SUBF(tx, px[i]), dy = SUBF(ty, py[i]);
        dist[i] = __fsqrt_rn(ADDF(MULF(dx,dx), MULF(dy,dy)));
        s_dist[i][tid] = dist[i];
    }

    // Stable two-min scan (branchless): closest (bi,bx,by) and 2nd (si)
    float bd = dist[0], bx = px[0], by = py[0], sd = INFINITY;
    int bi = 0, si = 0;
    #pragma unroll
    for (int i = 1; i < 16; i++) {
        bool lb = dist[i] < bd;
        bool ls = dist[i] < sd;
        sd = lb ? bd : (ls ? dist[i] : sd);
        si = lb ? bi : (ls ? i       : si);
        bd = lb ? dist[i] : bd;
        bx = lb ? px[i]   : bx;
        by = lb ? py[i]   : by;
        bi = lb ? i       : bi;
    }

    // per-point: ex/ey/u regs for the hot loop; exact d00/d02 -> smem only.
    float v2x = SUBF(tx, bx), v2y = SUBF(ty, by);
    float ex[16], ey[16], u[16];
    #pragma unroll
    for (int i = 0; i < 16; i++) {
        float e0 = SUBF(px[i], bx), e1 = SUBF(py[i], by);
        ex[i] = e0; ey[i] = e1;
        u[i]  = v2x * e1 - v2y * e0;                 // approx path only
        float d00 = DOT2(e0, e1, e0, e1);            // exact bits
        float d02 = DOT2(e0, e1, v2x, v2y);          // exact bits
        s_e[i][tid] = make_float2(e0, e1);
        s_d[i][tid] = make_float2(d00, d02);
    }

    // ---- hot loop: cross-form approximate scoring, full-float top-2 ----
    float s1 = INFINITY, s2 = INFINITY;
    int   id1 = -1,      id2 = -1;

    #pragma unroll
    for (int i = 0; i < 15; i++) {
        float exi = ex[i], eyi = ey[i], ui = u[i];
        float aui = fabsf(ui);
        #pragma unroll
        for (int j = i + 1; j < 16; j++) {
            float c  = exi * ey[j] - eyi * ex[j];   // pairs w/ closest: c == 0
            float c2 = c * c;
            float e  = 1e-4f * c2;                  // weight-space margin
            float q  = c - u[j] + ui;               // ~ p0 * c
            float gU = __fmaf_rn(u[j], c, e);       // p2 > -1e-4
            float gV = __fmaf_rn(-ui,  c, e);       // p1 > -1e-4
            float gQ = __fmaf_rn(q,    c, e);       // p0 > -1e-4
            float m  = fminf(fminf(gU, gV), gQ);
            float am = fmaxf(fmaxf(aui, fabsf(u[j])), fabsf(q));
            float r;  asm("rcp.approx.f32 %0, %1;" : "=f"(r) : "f"(c2));
            float s  = (am * am) * r;
            bool valid = m > 0.0f;
            bool b1 = valid && (s < s1);
            bool b2 = valid && (s < s2);
            int code = i * 16 + j;
            s2  = b1 ? s1  : (b2 ? s    : s2);
            id2 = b1 ? id1 : (b2 ? code : id2);
            s1  = b1 ? s    : s1;
            id1 = b1 ? code : id1;
        }
    }

    // ---- exact resolution of top-2 candidates (smem gather) ----
    float w0 = 0.f, w1 = 0.f, w2 = 0.f;
    int   o1 = si, o2 = si;
    float bestS = INFINITY;

    #pragma unroll
    for (int c = 0; c < 2; c++) {
        int code = (c == 0) ? id1 : id2;
        if (code >= 0) {
            int ip = code >> 4, jp = code & 15;
            float2 eiv = s_e[ip][tid], ejv = s_e[jp][tid];
            float2 div = s_d[ip][tid], djv = s_d[jp][tid];
            float  di  = s_dist[ip][tid], dj = s_dist[jp][tid];
            float d01 = DOT2(eiv.x, eiv.y, ejv.x, ejv.y);       // exact bits
            float den = SUBF(MULF(div.x,djv.x), MULF(d01,d01));
            if (den == 0.0f) den = 1e-10f;
            float nA = SUBF(MULF(div.y,djv.x), MULF(d01,djv.y));
            float nB = SUBF(MULF(div.x,djv.y), MULF(d01,div.y));
            bool candx = (den > 0.0f) ? (nA > 0.0f && nB > 0.0f)
                                      : (nA < 0.0f && nB < 0.0f);
            if (candx) {
                float pA = DIVF(nA, den);                       // exact IEEE
                float pB = DIVF(nB, den);
                float m2  = fmaxf(MULF(pA,pA), MULF(pB,pB));
                float p0i = SUBF(SUBF(1.0f, pA), pB);
                float p0j = SUBF(SUBF(1.0f, pB), pA);
                float siS = (p0i > 0.f) ? fmaxf(MULF(p0i,p0i), m2) : INFINITY;
                float sjS = (p0j > 0.f) ? fmaxf(MULF(p0j,p0j), m2) : INFINITY;
                bool iFirst = (di <= dj);
                float sLow  = iFirst ? siS : sjS;
                float sHigh = iFirst ? sjS : siS;
                bool pickLow = (sLow <= sHigh);
                float s = pickLow ? sLow : sHigh;
                if (s < bestS) {
                    bestS = s;
                    bool icell = pickLow ? iFirst : !iFirst;
                    if (icell) { w0 = p0i; w1 = pA; w2 = pB; o1 = ip; o2 = jp; }
                    else       { w0 = p0j; w1 = pB; w2 = pA; o1 = jp; o2 = ip; }
                }
            }
        }
    }

    // ---- cold safety net: no candidate OR both exactly rejected ----
    if (!(bestS < INFINITY)) {
        #pragma unroll 1
        for (int ip = 0; ip < 15; ip++) {
            float2 eiv = s_e[ip][tid];
            float2 div = s_d[ip][tid];
            float  di  = s_dist[ip][tid];
            #pragma unroll 1
            for (int jp = ip + 1; jp < 16; jp++) {
                float2 ejv = s_e[jp][tid];
                float2 djv = s_d[jp][tid];
                float  dj  = s_dist[jp][tid];
                float d01 = DOT2(eiv.x, eiv.y, ejv.x, ejv.y);
                float den = SUBF(MULF(div.x,djv.x), MULF(d01,d01));
                if (den == 0.0f) den = 1e-10f;
                float nA = SUBF(MULF(div.y,djv.x), MULF(d01,djv.y));
                float nB = SUBF(MULF(div.x,djv.y), MULF(d01,div.y));
                bool candx = (den > 0.0f) ? (nA > 0.0f && nB > 0.0f)
                                          : (nA < 0.0f && nB < 0.0f);
                if (candx) {
                    float pA = DIVF(nA, den);
                    float pB = DIVF(nB, den);
                    float m2  = fmaxf(MULF(pA,pA), MULF(pB,pB));
                    float p0i = SUBF(SUBF(1.0f, pA), pB);
                    float p0j = SUBF(SUBF(1.0f, pB), pA);
                    float siS = (p0i > 0.f) ? fmaxf(MULF(p0i,p0i), m2) : INFINITY;
                    float sjS = (p0j > 0.f) ? fmaxf(MULF(p0j,p0j), m2) : INFINITY;
                    bool iFirst = (di <= dj);
                    float sLow  = iFirst ? siS : sjS;
                    float sHigh = iFirst ? sjS : siS;
                    bool pickLow = (sLow <= sHigh);
                    float s = pickLow ? sLow : sHigh;
                    if (s < bestS) {
                        bestS = s;
                        bool icell = pickLow ? iFirst : !iFirst;
                        if (icell) { w0 = p0i; w1 = pA; w2 = pB; o1 = ip; o2 = jp; }
                        else       { w0 = p0j; w1 = pB; w2 = pA; o1 = jp; o2 = ip; }
                    }
                }
            }
        }
        if (!(bestS < INFINITY)) {   // truly no valid pair: reference fallback
            w0 = 0.f; w1 = 0.f; w2 = 0.f; o1 = si; o2 = si;
        }
    }

    float* ow = out + (size_t)gid * 3;
    ow[0] = w0; ow[1] = w1; ow[2] = w2;
    float* oi = out + (size_t)V * RA * 3 + (size_t)gid * 3;
    oi[0] = (float)bi; oi[1] = (float)o1; oi[2] = (float)o2;
}

extern "C" void kernel_launch(void* const* d_in, const int* in_sizes, int n_in,
                              void* d_out, int out_size)
{
    const float* tmpl = (const float*)d_in[0];   // (5,8,2) = 80 floats
    const float* proj = (const float*)d_in[1];   // (V,16,2)
    int V = in_sizes[1] / 32;
    int total = V * 40;
    int threads = 128;
    int blocks = (total + threads - 1) / threads;
    bc_kernel<<<blocks, threads>>>(tmpl, proj, (float*)d_out, V);
}

// round 11
// speedup vs baseline: 1.2744x; 1.0255x over previous
#include <cuda_runtime.h>
#include <math.h>

// BarycentricCoordinates: V=6000 x (R*A)=40 items, N=16 projections each.
// One thread per item.
//
// Bit-exactness model (validated R4-R10, rel_err == 0.0):
//  - einsum dot products (K=2): dot = __fmaf_rn(y,y', __fmul_rn(x,x'))
//  - all other elementwise ops: strict IEEE mul/sub/div/sqrt, no contraction.
//
// R11: low-register-demand build.
//  - streaming prologue (no px/py/dist register arrays): two-min on the fly,
//    s_dist filled as computed; second L1-hot pass builds hot-loop operands.
//  - hot loop: cross form (c = e_i x e_j, u_k = v2 x e_k), conservative 1e-4
//    weight-space margin (borderline ACCEPTED), score on MUFU rcp, top-2 via
//    sortable int keys (code in low 8 mantissa bits, umin/umax).
//  - exact top-2 epilogue + cold exact full scan (smem), reference-bit math.
//  - __launch_bounds__(128,5): 102-reg cap with ~20 regs of scheduler slack.

#define MULF(a,b)   __fmul_rn((a),(b))
#define ADDF(a,b)   __fadd_rn((a),(b))
#define SUBF(a,b)   __fsub_rn((a),(b))
#define DIVF(a,b)   __fdiv_rn((a),(b))
#define DOT2(ax,ay,bx,by) __fmaf_rn((ay),(by), __fmul_rn((ax),(bx)))

#define KEY_SENTINEL 0x7FFFFFFFu

__global__ __launch_bounds__(128, 5)
void bc_kernel(const float* __restrict__ tmpl,
               const float* __restrict__ proj,
               float* __restrict__ out, int V)
{
    __shared__ float2 s_e[16][128];   // (ex, ey) exact bits
    __shared__ float2 s_d[16][128];   // (d00, d02) exact bits
    __shared__ float  s_dist[16][128];

    const int RA = 40;
    int tid = threadIdx.x;
    int gid = blockIdx.x * blockDim.x + tid;
    if (gid >= V * RA) return;        // exact grid: never diverges
    int v  = gid / RA;
    int ra = gid - v * RA;

    float tx = __ldg(tmpl + 2 * ra);
    float ty = __ldg(tmpl + 2 * ra + 1);
    const float4* pp = (const float4*)(proj + (size_t)v * 32);

    // ---- pass 1: streaming stable two-min over exact-bit dist ----
    float bd = INFINITY, sd = INFINITY, bx = 0.f, by = 0.f;
    int bi = 0, si = 0;
    #pragma unroll
    for (int k = 0; k < 8; k++) {
        float4 q = __ldg(pp + k);
        {
            float dx = SUBF(tx, q.x), dy = SUBF(ty, q.y);
            float d = __fsqrt_rn(ADDF(MULF(dx,dx), MULF(dy,dy)));
            s_dist[2*k][tid] = d;
            bool lb = d < bd, ls = d < sd;
            sd = lb ? bd : (ls ? d : sd);
            si = lb ? bi : (ls ? 2*k : si);
            bd = lb ? d : bd;  bx = lb ? q.x : bx;  by = lb ? q.y : by;
            bi = lb ? 2*k : bi;
        }
        {
            float dx = SUBF(tx, q.z), dy = SUBF(ty, q.w);
            float d = __fsqrt_rn(ADDF(MULF(dx,dx), MULF(dy,dy)));
            s_dist[2*k+1][tid] = d;
            bool lb = d < bd, ls = d < sd;
            sd = lb ? bd : (ls ? d : sd);
            si = lb ? bi : (ls ? 2*k+1 : si);
            bd = lb ? d : bd;  bx = lb ? q.z : bx;  by = lb ? q.w : by;
            bi = lb ? 2*k+1 : bi;
        }
    }

    // ---- pass 2 (L1-hot reload): hot-loop operands in regs, exact -> smem ----
    float v2x = SUBF(tx, bx), v2y = SUBF(ty, by);
    float ex[16], ey[16], u[16];
    #pragma unroll
    for (int k = 0; k < 8; k++) {
        float4 q = __ldg(pp + k);
        {
            float e0 = SUBF(q.x, bx), e1 = SUBF(q.y, by);
            ex[2*k] = e0; ey[2*k] = e1;
            u[2*k]  = v2x * e1 - v2y * e0;            // approx path only
            s_e[2*k][tid] = make_float2(e0, e1);
            s_d[2*k][tid] = make_float2(DOT2(e0,e1,e0,e1), DOT2(e0,e1,v2x,v2y));
        }
        {
            float e0 = SUBF(q.z, bx), e1 = SUBF(q.w, by);
            ex[2*k+1] = e0; ey[2*k+1] = e1;
            u[2*k+1]  = v2x * e1 - v2y * e0;
            s_e[2*k+1][tid] = make_float2(e0, e1);
            s_d[2*k+1][tid] = make_float2(DOT2(e0,e1,e0,e1), DOT2(e0,e1,v2x,v2y));
        }
    }

    // ---- hot loop: cross-form approx scoring, int-key top-2 ----
    unsigned k1 = KEY_SENTINEL, k2 = KEY_SENTINEL;

    #pragma unroll
    for (int i = 0; i < 15; i++) {
        float exi = ex[i], eyi = ey[i], ui = u[i];
        float aui = fabsf(ui);
        #pragma unroll
        for (int j = i + 1; j < 16; j++) {
            float c  = exi * ey[j] - eyi * ex[j];   // pairs w/ closest: c == 0
            float c2 = c * c;
            float e  = 1e-4f * c2;                  // weight-space margin
            float q  = c - u[j] + ui;               // ~ p0 * c
            float gU = __fmaf_rn(u[j], c, e);       // p2 > -1e-4
            float gV = __fmaf_rn(-ui,  c, e);       // p1 > -1e-4
            float gQ = __fmaf_rn(q,    c, e);       // p0 > -1e-4
            float m  = fminf(fminf(gU, gV), gQ);
            float am = fmaxf(fmaxf(aui, fabsf(u[j])), fabsf(q));
            float r;  asm("rcp.approx.f32 %0, %1;" : "=f"(r) : "f"(c2));
            float s  = (am * am) * r;               // >= 0 when valid
            unsigned key = (m > 0.0f)
                ? ((__float_as_uint(s) & 0xFFFFFF00u) | (unsigned)(i * 16 + j))
                : KEY_SENTINEL;
            unsigned mx = umax(k1, key);
            k1 = umin(k1, key);
            k2 = umin(k2, mx);
        }
    }

    // ---- exact resolution of top-2 candidates (smem gather) ----
    float w0 = 0.f, w1 = 0.f, w2 = 0.f;
    int   o1 = si, o2 = si;
    float bestS = INFINITY;

    #pragma unroll
    for (int c = 0; c < 2; c++) {
        unsigned key = (c == 0) ? k1 : k2;
        if (key != KEY_SENTINEL) {
            int code = (int)(key & 255u);
            int ip = code >> 4, jp = code & 15;
            float2 eiv = s_e[ip][tid], ejv = s_e[jp][tid];
            float2 div = s_d[ip][tid], djv = s_d[jp][tid];
            float  di  = s_dist[ip][tid], dj = s_dist[jp][tid];
            float d01 = DOT2(eiv.x, eiv.y, ejv.x, ejv.y);       // exact bits
            float den = SUBF(MULF(div.x,djv.x), MULF(d01,d01));
            if (den == 0.0f) den = 1e-10f;
            float nA = SUBF(MULF(div.y,djv.x), MULF(d01,djv.y));
            float nB = SUBF(MULF(div.x,djv.y), MULF(d01,div.y));
            bool candx = (den > 0.0f) ? (nA > 0.0f && nB > 0.0f)
                                      : (nA < 0.0f && nB < 0.0f);
            if (candx) {
                float pA = DIVF(nA, den);                       // exact IEEE
                float pB = DIVF(nB, den);
                float m2  = fmaxf(MULF(pA,pA), MULF(pB,pB));
                float p0i = SUBF(SUBF(1.0f, pA), pB);
                float p0j = SUBF(SUBF(1.0f, pB), pA);
                float siS = (p0i > 0.f) ? fmaxf(MULF(p0i,p0i), m2) : INFINITY;
                float sjS = (p0j > 0.f) ? fmaxf(MULF(p0j,p0j), m2) : INFINITY;
                bool iFirst = (di <= dj);
                float sLow  = iFirst ? siS : sjS;
                float sHigh = iFirst ? sjS : siS;
                bool pickLow = (sLow <= sHigh);
                float s = pickLow ? sLow : sHigh;
                if (s < bestS) {
                    bestS = s;
                    bool icell = pickLow ? iFirst : !iFirst;
                    if (icell) { w0 = p0i; w1 = pA; w2 = pB; o1 = ip; o2 = jp; }
                    else       { w0 = p0j; w1 = pB; w2 = pA; o1 = jp; o2 = ip; }
                }
            }
        }
    }

    // ---- cold safety net: no candidate OR both exactly rejected ----
    if (!(bestS < INFINITY)) {
        #pragma unroll 1
        for (int ip = 0; ip < 15; ip++) {
            float2 eiv = s_e[ip][tid];
            float2 div = s_d[ip][tid];
            float  di  = s_dist[ip][tid];
            #pragma unroll 1
            for (int jp = ip + 1; jp < 16; jp++) {
                float2 ejv = s_e[jp][tid];
                float2 djv = s_d[jp][tid];
                float  dj  = s_dist[jp][tid];
                float d01 = DOT2(eiv.x, eiv.y, ejv.x, ejv.y);
                float den = SUBF(MULF(div.x,djv.x), MULF(d01,d01));
                if (den == 0.0f) den = 1e-10f;
                float nA = SUBF(MULF(div.y,djv.x), MULF(d01,djv.y));
                float nB = SUBF(MULF(div.x,djv.y), MULF(d01,div.y));
                bool candx = (den > 0.0f) ? (nA > 0.0f && nB > 0.0f)
                                          : (nA < 0.0f && nB < 0.0f);
                if (candx) {
                    float pA = DIVF(nA, den);
                    float pB = DIVF(nB, den);
                    float m2  = fmaxf(MULF(pA,pA), MULF(pB,pB));
                    float p0i = SUBF(SUBF(1.0f, pA), pB);
                    float p0j = SUBF(SUBF(1.0f, pB), pA);
                    float siS = (p0i > 0.f) ? fmaxf(MULF(p0i,p0i), m2) : INFINITY;
                    float sjS = (p0j > 0.f) ? fmaxf(MULF(p0j,p0j), m2) : INFINITY;
                    bool iFirst = (di <= dj);
                    float sLow  = iFirst ? siS : sjS;
                    float sHigh = iFirst ? sjS : siS;
                    bool pickLow = (sLow <= sHigh);
                    float s = pickLow ? sLow : sHigh;
                    if (s < bestS) {
                        bestS = s;
                        bool icell = pickLow ? iFirst : !iFirst;
                        if (icell) { w0 = p0i; w1 = pA; w2 = pB; o1 = ip; o2 = jp; }
                        else       { w0 = p0j; w1 = pB; w2 = pA; o1 = jp; o2 = ip; }
                    }
                }
            }
        }
        if (!(bestS < INFINITY)) {   // truly no valid pair: reference fallback
            w0 = 0.f; w1 = 0.f; w2 = 0.f; o1 = si; o2 = si;
        }
    }

    float* ow = out + (size_t)gid * 3;
    ow[0] = w0; ow[1] = w1; ow[2] = w2;
    float* oi = out + (size_t)V * RA * 3 + (size_t)gid * 3;
    oi[0] = (float)bi; oi[1] = (float)o1; oi[2] = (float)o2;
}

extern "C" void kernel_launch(void* const* d_in, const int* in_sizes, int n_in,
                              void* d_out, int out_size)
{
    const float* tmpl = (const float*)d_in[0];   // (5,8,2) = 80 floats
    const float* proj = (const float*)d_in[1];   // (V,16,2)
    int V = in_sizes[1] / 32;
    int total = V * 40;
    int threads = 128;
    int blocks = (total + threads - 1) / threads;
    bc_kernel<<<blocks, threads>>>(tmpl, proj, (float*)d_out, V);
}

// round 12
// speedup vs baseline: 1.7445x; 1.3689x over previous
#include <cuda_runtime.h>
#include <math.h>

// BarycentricCoordinates: V=6000 x (R*A)=40 items, N=16 projections each.
// One thread per item.
//
// Bit-exactness model (validated in R4, rel_err == 0.0):
//  - einsum dot products (K=2): dot = __fmaf_rn(y,y', __fmul_rn(x,x'))
//  - all other elementwise ops: strict IEEE mul/sub/div/sqrt, no contraction.
//
// R12 = R6 (68.3us, no spills: L1 5.1%) with EXACTLY one change:
// __launch_bounds__(128, 4) -> (128, 5). Liveness audit says the hot loop
// needs ~90 regs, so the 102-reg cap should hold without spilling while
// raising occupancy 23.6% -> ~31% (smem 41KB x 5 = 205KB <= 228KB).
// Gram-form hot loop retained deliberately: its long dependency chains
// throttle ptxas over-pipelining (the spill source in R7-R11 cross forms).

#define MULF(a,b)   __fmul_rn((a),(b))
#define ADDF(a,b)   __fadd_rn((a),(b))
#define SUBF(a,b)   __fsub_rn((a),(b))
#define DIVF(a,b)   __fdiv_rn((a),(b))
#define DOT2(ax,ay,bx,by) __fmaf_rn((ay),(by), __fmul_rn((ax),(bx)))

__global__ __launch_bounds__(128, 5)
void bc_kernel(const float* __restrict__ tmpl,
               const float* __restrict__ proj,
               float* __restrict__ out, int V)
{
    __shared__ float2 s_e[16][128];   // (ex, ey)
    __shared__ float2 s_d[16][128];   // (d00, d02)
    __shared__ float  s_dist[16][128];

    const int RA = 40;
    int tid = threadIdx.x;
    int gid = blockIdx.x * blockDim.x + tid;
    if (gid >= V * RA) return;        // exact grid: never diverges
    int v  = gid / RA;
    int ra = gid - v * RA;

    float tx = __ldg(tmpl + 2 * ra);
    float ty = __ldg(tmpl + 2 * ra + 1);

    float px[16], py[16];
    const float4* pp = (const float4*)(proj + (size_t)v * 32);
    #pragma unroll
    for (int k = 0; k < 8; k++) {
        float4 q = __ldg(pp + k);
        px[2*k]   = q.x; py[2*k]   = q.y;
        px[2*k+1] = q.z; py[2*k+1] = q.w;
    }

    // dist: strict IEEE; stash in smem for the epilogue, regs die after scan.
    float dist[16];
    #pragma unroll
    for (int i = 0; i < 16; i++) {
        float dx = SUBF(tx, px[i]), dy = SUBF(ty, py[i]);
        dist[i] = __fsqrt_rn(ADDF(MULF(dx,dx), MULF(dy,dy)));
        s_dist[i][tid] = dist[i];
    }

    // Stable two-min scan (branchless): closest (bi,bx,by) and 2nd (si)
    float bd = dist[0], bx = px[0], by = py[0], sd = INFINITY;
    int bi = 0, si = 0;
    #pragma unroll
    for (int i = 1; i < 16; i++) {
        bool lb = dist[i] < bd;
        bool ls = dist[i] < sd;
        sd = lb ? bd : (ls ? dist[i] : sd);
        si = lb ? bi : (ls ? i       : si);
        bd = lb ? dist[i] : bd;
        bx = lb ? px[i]   : bx;
        by = lb ? py[i]   : by;
        bi = lb ? i       : bi;
    }

    float v2x = SUBF(tx, bx), v2y = SUBF(ty, by);
    float ex[16], ey[16], d00[16], d02[16];
    #pragma unroll
    for (int i = 0; i < 16; i++) {
        ex[i]  = SUBF(px[i], bx);
        ey[i]  = SUBF(py[i], by);
        d00[i] = DOT2(ex[i], ey[i], ex[i], ey[i]);
        d02[i] = DOT2(ex[i], ey[i], v2x, v2y);
        s_e[i][tid] = make_float2(ex[i], ey[i]);
        s_d[i][tid] = make_float2(d00[i], d02[i]);
    }

    // ---- approximate top-2 pair search: branch-free, scalar score ----
    float s1 = INFINITY, s2 = INFINITY;
    int   id1 = -1,      id2 = -1;

    #pragma unroll
    for (int i = 0; i < 15; i++) {
        #pragma unroll
        for (int j = i + 1; j < 16; j++) {
            float d01 = DOT2(ex[i], ey[i], ex[j], ey[j]);           // exact bits
            float den = SUBF(MULF(d00[i],d00[j]), MULF(d01,d01));   // exact bits
            den = (den == 0.0f) ? 1e-10f : den;
            float nA = SUBF(MULF(d02[i],d00[j]), MULF(d01,d02[j])); // exact bits
            float nB = SUBF(MULF(d00[i],d02[j]), MULF(d01,d02[i])); // exact bits
            float p0n  = SUBF(SUBF(den, nA), nB);     // ~ p0 * den (approx ok)
            float den2 = den * den;
            // sign-exact gates via products; conservative margin on p0
            float gA = nA * den;
            float gB = nB * den;
            float gP = __fmaf_rn(p0n, den, 1e-5f * den2);
            float m  = fminf(fminf(gA, gB), gP);
            float sNum = fmaxf(fmaxf(nA*nA, nB*nB), p0n*p0n);
            float r;
            asm("rcp.approx.f32 %0, %1;" : "=f"(r) : "f"(den2));    // MUFU pipe
            float s = sNum * r;
            s = (m > 0.0f) ? s : INFINITY;
            int code = i * 16 + j;
            bool b1 = s < s1;
            bool b2 = s < s2;
            s2  = b1 ? s1  : (b2 ? s    : s2);
            id2 = b1 ? id1 : (b2 ? code : id2);
            s1  = b1 ? s   : s1;
            id1 = b1 ? code : id1;
        }
    }

    // ---- exact epilogue: re-evaluate top-2 candidates bit-exactly ----
    float w0 = 0.f, w1 = 0.f, w2 = 0.f;
    int   o1 = si, o2 = si;
    float bestS = INFINITY;

    #pragma unroll
    for (int c = 0; c < 2; c++) {
        int code = (c == 0) ? id1 : id2;
        if (code >= 0) {
            int ip = code >> 4, jp = code & 15;
            float2 eiv = s_e[ip][tid], ejv = s_e[jp][tid];
            float2 div = s_d[ip][tid], djv = s_d[jp][tid];
            float  di  = s_dist[ip][tid], dj = s_dist[jp][tid];
            float d01 = DOT2(eiv.x, eiv.y, ejv.x, ejv.y);
            float den = SUBF(MULF(div.x,djv.x), MULF(d01,d01));
            if (den == 0.0f) den = 1e-10f;
            float nA = SUBF(MULF(div.y,djv.x), MULF(d01,djv.y));
            float nB = SUBF(MULF(div.x,djv.y), MULF(d01,div.y));
            bool candx = (den > 0.0f) ? (nA > 0.0f && nB > 0.0f)
                                      : (nA < 0.0f && nB < 0.0f);
            if (candx) {
                float pA = DIVF(nA, den);                 // exact IEEE divide
                float pB = DIVF(nB, den);
                float m2  = fmaxf(MULF(pA,pA), MULF(pB,pB));
                float p0i = SUBF(SUBF(1.0f, pA), pB);
                float p0j = SUBF(SUBF(1.0f, pB), pA);
                float siS = (p0i > 0.f) ? fmaxf(MULF(p0i,p0i), m2) : INFINITY;
                float sjS = (p0j > 0.f) ? fmaxf(MULF(p0j,p0j), m2) : INFINITY;
                bool iFirst = (di <= dj);
                float sLow  = iFirst ? siS : sjS;
                float sHigh = iFirst ? sjS : siS;
                bool pickLow = (sLow <= sHigh);
                float s = pickLow ? sLow : sHigh;
                if (s < bestS) {
                    bestS = s;
                    bool icell = pickLow ? iFirst : !iFirst;
                    if (icell) { w0 = p0i; w1 = pA; w2 = pB; o1 = ip; o2 = jp; }
                    else       { w0 = p0j; w1 = pB; w2 = pA; o1 = jp; o2 = ip; }
                }
            }
        }
    }

    if (!(bestS < INFINITY)) {   // no valid pair: reference fallback
        w0 = 0.f; w1 = 0.f; w2 = 0.f; o1 = si; o2 = si;
    }

    float* ow = out + (size_t)gid * 3;
    ow[0] = w0; ow[1] = w1; ow[2] = w2;
    float* oi = out + (size_t)V * RA * 3 + (size_t)gid * 3;
    oi[0] = (float)bi; oi[1] = (float)o1; oi[2] = (float)o2;
}

extern "C" void kernel_launch(void* const* d_in, const int* in_sizes, int n_in,
                              void* d_out, int out_size)
{
    const float* tmpl = (const float*)d_in[0];   // (5,8,2) = 80 floats
    const float* proj = (const float*)d_in[1];   // (V,16,2)
    int V = in_sizes[1] / 32;
    int total = V * 40;
    int threads = 128;
    int blocks = (total + threads - 1) / threads;
    bc_kernel<<<blocks, threads>>>(tmpl, proj, (float*)d_out, V);
}